// round 1
// baseline (speedup 1.0000x reference)
#include <cuda_runtime.h>
#include <math.h>

#define BB 512
#define TT 512

// Scratch for inter-layer activations (device globals: allocation-free rule).
__device__ float g_h1[(size_t)BB * TT * 32];   // layer1 output [B,T,32]
__device__ float g_h2[(size_t)BB * TT * 48];   // layer2 output [B,T,48]

__device__ __forceinline__ float sigmoidf_(float x) {
    return 1.0f / (1.0f + __expf(-x));
}

// ---------------------------------------------------------------------------
// Small-layer kernel: per-thread weights in registers.
// Threads = 4*H (one gate-column each). Each block owns Bc batch rows and
// loops over all T steps (batch rows are fully independent -> no grid sync).
// ---------------------------------------------------------------------------
template <int D, int H, int Bc>
__global__ void __launch_bounds__(4 * H, 1)
lstm_layer_regw(const float* __restrict__ x,     // [B,T,D]
                const float* __restrict__ Wih,   // [4H,D]
                const float* __restrict__ Whh,   // [4H,H]
                const float* __restrict__ bih,
                const float* __restrict__ bhh,
                float* __restrict__ out)         // [B,T,H]
{
    constexpr int G = 4 * H;
    const int col = threadIdx.x;                 // gate column 0..4H-1
    const int b0  = blockIdx.x * Bc;

    __shared__ __align__(16) float x_sm[Bc][D];
    __shared__ __align__(16) float h_sm[Bc][H];
    __shared__ float gate_sm[Bc][G];

    // Per-thread weight row in registers.
    float wx[D], wh[H];
#pragma unroll
    for (int k = 0; k < D; k++) wx[k] = __ldg(&Wih[col * D + k]);
#pragma unroll
    for (int k = 0; k < H; k++) wh[k] = __ldg(&Whh[col * H + k]);
    const float bsum = __ldg(&bih[col]) + __ldg(&bhh[col]);

    for (int i = col; i < Bc * H; i += G) ((float*)h_sm)[i] = 0.0f;
    float c[Bc];
#pragma unroll
    for (int r = 0; r < Bc; r++) c[r] = 0.0f;

    for (int t = 0; t < TT; t++) {
        __syncthreads();  // prev-iter h_sm reads done before x_sm rewrite
        for (int i = col; i < Bc * D; i += G) {
            int rr = i / D, kk = i % D;
            x_sm[rr][kk] = x[((size_t)(b0 + rr) * TT + t) * D + kk];
        }
        __syncthreads();

        float acc[Bc];
#pragma unroll
        for (int r = 0; r < Bc; r++) acc[r] = bsum;

#pragma unroll
        for (int r = 0; r < Bc; r++) {
            const float4* x4 = reinterpret_cast<const float4*>(&x_sm[r][0]);
#pragma unroll
            for (int k4 = 0; k4 < D / 4; k4++) {
                float4 v = x4[k4];
                acc[r] += wx[4 * k4 + 0] * v.x + wx[4 * k4 + 1] * v.y +
                          wx[4 * k4 + 2] * v.z + wx[4 * k4 + 3] * v.w;
            }
            const float4* h4 = reinterpret_cast<const float4*>(&h_sm[r][0]);
#pragma unroll
            for (int k4 = 0; k4 < H / 4; k4++) {
                float4 v = h4[k4];
                acc[r] += wh[4 * k4 + 0] * v.x + wh[4 * k4 + 1] * v.y +
                          wh[4 * k4 + 2] * v.z + wh[4 * k4 + 3] * v.w;
            }
        }
#pragma unroll
        for (int r = 0; r < Bc; r++) gate_sm[r][col] = acc[r];
        __syncthreads();

        if (col < H) {
#pragma unroll
            for (int r = 0; r < Bc; r++) {
                float i_ = sigmoidf_(gate_sm[r][col]);
                float f_ = sigmoidf_(gate_sm[r][H + col]);
                float g_ = tanhf(gate_sm[r][2 * H + col]);
                float o_ = sigmoidf_(gate_sm[r][3 * H + col]);
                c[r] = f_ * c[r] + i_ * g_;
                float h = o_ * tanhf(c[r]);
                h_sm[r][col] = h;
                out[((size_t)(b0 + r) * TT + t) * H + col] = h;
            }
        }
    }
}

// ---------------------------------------------------------------------------
// Big-layer kernel (layer 3, D=48 H=128): weights too big for regs/smem ->
// streamed from global via L1 each step, k-outer / row-inner so each weight
// fetch feeds Bc FMAs (keeps L1 below the FMA floor).
// ---------------------------------------------------------------------------
template <int D, int H, int Bc>
__global__ void __launch_bounds__(4 * H, 2)
lstm_layer_big(const float* __restrict__ x,      // [B,T,D]
               const float* __restrict__ Wih,    // [4H,D]
               const float* __restrict__ Whh,    // [4H,H]
               const float* __restrict__ bih,
               const float* __restrict__ bhh,
               float* __restrict__ out,          // [B,T,H]
               float* __restrict__ hn)           // [B,H]
{
    constexpr int G = 4 * H;   // 512
    const int col = threadIdx.x;
    const int b0  = blockIdx.x * Bc;

    __shared__ __align__(16) float x_sm[Bc][D];
    __shared__ __align__(16) float h_sm[Bc][H];
    __shared__ float gate_sm[Bc][G];

    const float4* wx4 = reinterpret_cast<const float4*>(Wih + (size_t)col * D);
    const float4* wh4 = reinterpret_cast<const float4*>(Whh + (size_t)col * H);
    const float bsum = __ldg(&bih[col]) + __ldg(&bhh[col]);

    for (int i = col; i < Bc * H; i += G) ((float*)h_sm)[i] = 0.0f;
    float c[Bc];
#pragma unroll
    for (int r = 0; r < Bc; r++) c[r] = 0.0f;

    for (int t = 0; t < TT; t++) {
        __syncthreads();
        for (int i = col; i < Bc * D; i += G) {
            int rr = i / D, kk = i % D;
            x_sm[rr][kk] = x[((size_t)(b0 + rr) * TT + t) * D + kk];
        }
        __syncthreads();

        float acc[Bc];
#pragma unroll
        for (int r = 0; r < Bc; r++) acc[r] = bsum;

        // input projection: weight chunk register-cached, reused over Bc rows
#pragma unroll 4
        for (int k4 = 0; k4 < D / 4; k4++) {
            float4 w = __ldg(wx4 + k4);
#pragma unroll
            for (int r = 0; r < Bc; r++) {
                float4 v = reinterpret_cast<const float4*>(&x_sm[r][0])[k4];
                acc[r] += w.x * v.x + w.y * v.y + w.z * v.z + w.w * v.w;
            }
        }
        // recurrent projection
#pragma unroll 8
        for (int k4 = 0; k4 < H / 4; k4++) {
            float4 w = __ldg(wh4 + k4);
#pragma unroll
            for (int r = 0; r < Bc; r++) {
                float4 v = reinterpret_cast<const float4*>(&h_sm[r][0])[k4];
                acc[r] += w.x * v.x + w.y * v.y + w.z * v.z + w.w * v.w;
            }
        }
#pragma unroll
        for (int r = 0; r < Bc; r++) gate_sm[r][col] = acc[r];
        __syncthreads();

        if (col < H) {
#pragma unroll
            for (int r = 0; r < Bc; r++) {
                float i_ = sigmoidf_(gate_sm[r][col]);
                float f_ = sigmoidf_(gate_sm[r][H + col]);
                float g_ = tanhf(gate_sm[r][2 * H + col]);
                float o_ = sigmoidf_(gate_sm[r][3 * H + col]);
                c[r] = f_ * c[r] + i_ * g_;
                float h = o_ * tanhf(c[r]);
                h_sm[r][col] = h;
                out[((size_t)(b0 + r) * TT + t) * H + col] = h;
                if (t == TT - 1) hn[(size_t)(b0 + r) * H + col] = h;
            }
        }
    }
}

extern "C" void kernel_launch(void* const* d_in, const int* in_sizes, int n_in,
                              void* d_out, int out_size)
{
    const float* z    = (const float*)d_in[0];
    const float* Wih1 = (const float*)d_in[1];
    const float* Whh1 = (const float*)d_in[2];
    const float* bih1 = (const float*)d_in[3];
    const float* bhh1 = (const float*)d_in[4];
    const float* Wih2 = (const float*)d_in[5];
    const float* Whh2 = (const float*)d_in[6];
    const float* bih2 = (const float*)d_in[7];
    const float* bhh2 = (const float*)d_in[8];
    const float* Wih3 = (const float*)d_in[9];
    const float* Whh3 = (const float*)d_in[10];
    const float* bih3 = (const float*)d_in[11];
    const float* bhh3 = (const float*)d_in[12];

    float* dec = (float*)d_out;                          // [B,T,128]
    float* hn  = dec + (size_t)BB * TT * 128;            // [1,B,128]

    float* h1 = nullptr;
    float* h2 = nullptr;
    cudaGetSymbolAddress((void**)&h1, g_h1);
    cudaGetSymbolAddress((void**)&h2, g_h2);

    // Layer 1: 64 -> 32.  Bc=2 -> 256 blocks x 128 threads.
    lstm_layer_regw<64, 32, 2><<<BB / 2, 128>>>(z, Wih1, Whh1, bih1, bhh1, h1);
    // Layer 2: 32 -> 48.  Bc=2 -> 256 blocks x 192 threads.
    lstm_layer_regw<32, 48, 2><<<BB / 2, 192>>>(h1, Wih2, Whh2, bih2, bhh2, h2);
    // Layer 3: 48 -> 128. Bc=4 -> 128 blocks x 512 threads.
    lstm_layer_big<48, 128, 4><<<BB / 4, 512>>>(h2, Wih3, Whh3, bih3, bhh3, dec, hn);
}

// round 2
// speedup vs baseline: 2.5303x; 2.5303x over previous
#include <cuda_runtime.h>
#include <math.h>

#define BB 512
#define TT 512

// ---------------- device scratch (allocation-free rule) ----------------
__device__ float g_gx[(size_t)TT * BB * 512];   // gate pre-activations, reused per layer (512MB)
__device__ float g_h1[(size_t)BB * TT * 32];    // layer1 output
__device__ float g_h2[(size_t)BB * TT * 48];    // layer2 output
__device__ float g_Wt3[128 * 512];              // Whh3 transposed [k][col]

// ---------------- f32x2 helpers ----------------
__device__ __forceinline__ unsigned long long pk2(float a, float b) {
    unsigned long long r;
    asm("mov.b64 %0, {%1,%2};" : "=l"(r) : "f"(a), "f"(b));
    return r;
}
__device__ __forceinline__ void fma2_(unsigned long long& d, unsigned long long a,
                                      unsigned long long b) {
    asm("fma.rn.f32x2 %0, %1, %2, %0;" : "+l"(d) : "l"(a), "l"(b));
}
__device__ __forceinline__ unsigned long long add2_(unsigned long long a,
                                                    unsigned long long b) {
    unsigned long long r;
    asm("add.rn.f32x2 %0, %1, %2;" : "=l"(r) : "l"(a), "l"(b));
    return r;
}
__device__ __forceinline__ float sig_(float x) { return 1.0f / (1.0f + __expf(-x)); }
__device__ __forceinline__ float th_(float x) { return 1.0f - 2.0f / (__expf(2.0f * x) + 1.0f); }

// ---------------------------------------------------------------------------
// Input projection: gx[t][b][0:N] = x[b][t][:] @ Wih.T + (bih+bhh).
// Thread = output column, weights in registers, x tile broadcast from smem.
// ---------------------------------------------------------------------------
template <int D, int N, int MT>
__global__ void __launch_bounds__(N)
lstm_proj(const float* __restrict__ x, const float* __restrict__ Wih,
          const float* __restrict__ bih, const float* __restrict__ bhh,
          float* __restrict__ gx)
{
    const int col = threadIdx.x;
    float w[D];
#pragma unroll
    for (int k = 0; k < D; k++) w[k] = __ldg(&Wih[col * D + k]);
    const float bsum = __ldg(&bih[col]) + __ldg(&bhh[col]);

    __shared__ float4 xs[MT][D / 4];
    const int ntiles = (BB * TT) / MT;

    for (int tile = blockIdx.x; tile < ntiles; tile += gridDim.x) {
        __syncthreads();
        for (int i = col; i < MT * D / 4; i += N)
            ((float4*)xs)[i] = ((const float4*)x)[(size_t)tile * (MT * D / 4) + i];
        __syncthreads();

#pragma unroll 2
        for (int r = 0; r < MT; r++) {
            float a0 = bsum, a1 = 0.f, a2 = 0.f, a3 = 0.f;
#pragma unroll
            for (int k4 = 0; k4 < D / 4; k4++) {
                float4 v = xs[r][k4];
                a0 = fmaf(w[4 * k4 + 0], v.x, a0);
                a1 = fmaf(w[4 * k4 + 1], v.y, a1);
                a2 = fmaf(w[4 * k4 + 2], v.z, a2);
                a3 = fmaf(w[4 * k4 + 3], v.w, a3);
            }
            int m = tile * MT + r;
            int b = m >> 9, t = m & 511;         // T = 512
            gx[((size_t)t * BB + b) * N + col] = (a0 + a1) + (a2 + a3);
        }
    }
}

// ---------------------------------------------------------------------------
// Small-layer recurrence (L1: H=32, L2: H=48). 2 batch rows per block packed
// as f32x2; per-thread Whh row pre-packed in registers. Block = 4H threads.
// ---------------------------------------------------------------------------
template <int H>
__global__ void __launch_bounds__(4 * H)
lstm_recur_small(const float* __restrict__ gx,   // [T][B][4H]
                 const float* __restrict__ Whh,  // [4H][H]
                 float* __restrict__ out)        // [B][T][H]
{
    constexpr int G = 4 * H;
    const int col = threadIdx.x;
    const int b0 = blockIdx.x * 2;

    unsigned long long wh2[H];
#pragma unroll
    for (int k = 0; k < H; k++) {
        float w = __ldg(&Whh[col * H + k]);
        wh2[k] = pk2(w, w);
    }

    __shared__ unsigned long long h2[H];   // per k: packed (row0,row1) h
    __shared__ unsigned long long g2[G];   // gate exchange
    if (col < H) h2[col] = 0ull;

    // epilogue mapping: threads col < 2H each own one (hcol,row)
    const int erow = col & 1, ecol = col >> 1;
    float c = 0.f;
    __syncthreads();

    for (int t = 0; t < TT; t++) {
        const float* gp = gx + ((size_t)t * BB + b0) * G + col;
        float gx0 = gp[0], gx1 = gp[G];      // loads in flight over k-loop
        unsigned long long a0 = 0ull, a1 = 0ull, a2 = 0ull, a3 = 0ull;
#pragma unroll
        for (int k = 0; k < H; k += 4) {
            fma2_(a0, wh2[k + 0], h2[k + 0]);
            fma2_(a1, wh2[k + 1], h2[k + 1]);
            fma2_(a2, wh2[k + 2], h2[k + 2]);
            fma2_(a3, wh2[k + 3], h2[k + 3]);
        }
        g2[col] = add2_(add2_(add2_(a0, a1), add2_(a2, a3)), pk2(gx0, gx1));
        __syncthreads();

        if (col < 2 * H) {
            const float* gf = (const float*)g2;   // float idx = 2*gatecol + row
            float gi = gf[2 * ecol + erow];
            float gF = gf[2 * (H + ecol) + erow];
            float gg = gf[2 * (2 * H + ecol) + erow];
            float go = gf[2 * (3 * H + ecol) + erow];
            c = sig_(gF) * c + sig_(gi) * th_(gg);
            float h = sig_(go) * th_(c);
            ((float*)h2)[2 * ecol + erow] = h;
            out[((size_t)(b0 + erow) * TT + t) * H + ecol] = h;
        }
        __syncthreads();
    }
}

// ---------------------------------------------------------------------------
// Layer-3 recurrence: H=128, 4H=512 cols, Bc=4 rows (2 f32x2 pairs) per block,
// 128 blocks x 256 threads. Transposed weights: first KS k-rows in smem
// (coalesced, conflict-free), last (128-KS) k-rows permanently in registers.
// ---------------------------------------------------------------------------
#define KS3 108
#define SMEM_BIG (KS3 * 512 * 4 + 128 * 16 + 512 * 16)   // 231,424 B

__global__ void __launch_bounds__(256)
lstm_recur_big(const float* __restrict__ gx,   // [T][B][512]
               const float* __restrict__ Wt,   // [128][512] transposed Whh3
               float* __restrict__ out,        // [B][T][128]
               float* __restrict__ hn)         // [B][128]
{
    extern __shared__ char sraw[];
    float2* Wsm = (float2*)sraw;                                   // [KS3][256]
    unsigned long long* hp = (unsigned long long*)(sraw + KS3 * 512 * 4);        // [128][2]
    unsigned long long* g4 = (unsigned long long*)(sraw + KS3 * 512 * 4 + 2048); // [512][2]

    const int tid = threadIdx.x;
    const int b0 = blockIdx.x * 4;
    const int c0 = tid * 2;                     // this thread's 2 gate columns

    // load smem-resident weights (coalesced)
    for (int i = tid; i < KS3 * 128; i += 256)
        ((float4*)Wsm)[i] = ((const float4*)Wt)[i];
    // register-resident tail weights (loop-invariant over t)
    float2 wg[128 - KS3];
#pragma unroll
    for (int j = 0; j < 128 - KS3; j++)
        wg[j] = *(const float2*)(Wt + (size_t)(KS3 + j) * 512 + c0);

    hp[tid & 255] = 0ull;  // 256 entries == 128*2

    // epilogue mapping: thread owns h-col ecol, rows (2*erp, 2*erp+1)
    const int ecol = tid & 127, erp = tid >> 7;
    float cA = 0.f, cB = 0.f;
    __syncthreads();

    for (int t = 0; t < TT; t++) {
        const float* gb = gx + ((size_t)t * BB + b0) * 512 + c0;
        float2 gr0 = *(const float2*)(gb);
        float2 gr1 = *(const float2*)(gb + 512);
        float2 gr2 = *(const float2*)(gb + 1024);
        float2 gr3 = *(const float2*)(gb + 1536);

        unsigned long long A00 = 0, A01 = 0, A10 = 0, A11 = 0;
        unsigned long long B00 = 0, B01 = 0, B10 = 0, B11 = 0;

#pragma unroll 4
        for (int k = 0; k < KS3; k += 2) {
            {
                float2 w = Wsm[k * 256 + tid];
                ulonglong2 h = ((const ulonglong2*)hp)[k];
                unsigned long long w0 = pk2(w.x, w.x), w1 = pk2(w.y, w.y);
                fma2_(A00, w0, h.x); fma2_(A01, w0, h.y);
                fma2_(A10, w1, h.x); fma2_(A11, w1, h.y);
            }
            {
                float2 w = Wsm[(k + 1) * 256 + tid];
                ulonglong2 h = ((const ulonglong2*)hp)[k + 1];
                unsigned long long w0 = pk2(w.x, w.x), w1 = pk2(w.y, w.y);
                fma2_(B00, w0, h.x); fma2_(B01, w0, h.y);
                fma2_(B10, w1, h.x); fma2_(B11, w1, h.y);
            }
        }
#pragma unroll
        for (int j = 0; j < 128 - KS3; j++) {
            float2 w = wg[j];
            ulonglong2 h = ((const ulonglong2*)hp)[KS3 + j];
            unsigned long long w0 = pk2(w.x, w.x), w1 = pk2(w.y, w.y);
            if (j & 1) { fma2_(B00, w0, h.x); fma2_(B01, w0, h.y);
                         fma2_(B10, w1, h.x); fma2_(B11, w1, h.y); }
            else       { fma2_(A00, w0, h.x); fma2_(A01, w0, h.y);
                         fma2_(A10, w1, h.x); fma2_(A11, w1, h.y); }
        }

        ulonglong2 r0, r1;
        r0.x = add2_(add2_(A00, B00), pk2(gr0.x, gr1.x));
        r0.y = add2_(add2_(A01, B01), pk2(gr2.x, gr3.x));
        r1.x = add2_(add2_(A10, B10), pk2(gr0.y, gr1.y));
        r1.y = add2_(add2_(A11, B11), pk2(gr2.y, gr3.y));
        ((ulonglong2*)g4)[c0]     = r0;
        ((ulonglong2*)g4)[c0 + 1] = r1;
        __syncthreads();

        {
            const float2* gf2 = (const float2*)g4;  // idx = gatecol*2 + rowpair
            float2 gi = gf2[(ecol      ) * 2 + erp];
            float2 gF = gf2[(ecol + 128) * 2 + erp];
            float2 gg = gf2[(ecol + 256) * 2 + erp];
            float2 go = gf2[(ecol + 384) * 2 + erp];
            cA = sig_(gF.x) * cA + sig_(gi.x) * th_(gg.x);
            cB = sig_(gF.y) * cB + sig_(gi.y) * th_(gg.y);
            float h0 = sig_(go.x) * th_(cA);
            float h1 = sig_(go.y) * th_(cB);
            hp[ecol * 2 + erp] = pk2(h0, h1);
            out[((size_t)(b0 + 2 * erp) * TT + t) * 128 + ecol] = h0;
            out[((size_t)(b0 + 2 * erp + 1) * TT + t) * 128 + ecol] = h1;
            if (t == TT - 1) {
                hn[(size_t)(b0 + 2 * erp) * 128 + ecol] = h0;
                hn[(size_t)(b0 + 2 * erp + 1) * 128 + ecol] = h1;
            }
        }
        __syncthreads();
    }
}

// ---------------------------------------------------------------------------
__global__ void transposeW3(const float* __restrict__ Whh, float* __restrict__ Wt)
{
    int i = blockIdx.x * 256 + threadIdx.x;     // 65536 elements
    if (i < 128 * 512) {
        int k = i >> 9, col = i & 511;
        Wt[i] = Whh[col * 128 + k];
    }
}

// ---------------------------------------------------------------------------
extern "C" void kernel_launch(void* const* d_in, const int* in_sizes, int n_in,
                              void* d_out, int out_size)
{
    const float* z    = (const float*)d_in[0];
    const float* Wih1 = (const float*)d_in[1];
    const float* Whh1 = (const float*)d_in[2];
    const float* bih1 = (const float*)d_in[3];
    const float* bhh1 = (const float*)d_in[4];
    const float* Wih2 = (const float*)d_in[5];
    const float* Whh2 = (const float*)d_in[6];
    const float* bih2 = (const float*)d_in[7];
    const float* bhh2 = (const float*)d_in[8];
    const float* Wih3 = (const float*)d_in[9];
    const float* Whh3 = (const float*)d_in[10];
    const float* bih3 = (const float*)d_in[11];
    const float* bhh3 = (const float*)d_in[12];

    float* dec = (float*)d_out;                        // [B,T,128]
    float* hn  = dec + (size_t)BB * TT * 128;          // [1,B,128]

    float *gx, *h1, *h2, *Wt3;
    cudaGetSymbolAddress((void**)&gx, g_gx);
    cudaGetSymbolAddress((void**)&h1, g_h1);
    cudaGetSymbolAddress((void**)&h2, g_h2);
    cudaGetSymbolAddress((void**)&Wt3, g_Wt3);

    cudaFuncSetAttribute(lstm_recur_big,
                         cudaFuncAttributeMaxDynamicSharedMemorySize, SMEM_BIG);

    transposeW3<<<256, 256>>>(Whh3, Wt3);

    // Layer 1: 64 -> 32
    lstm_proj<64, 128, 32><<<2048, 128>>>(z, Wih1, bih1, bhh1, gx);
    lstm_recur_small<32><<<BB / 2, 128>>>(gx, Whh1, h1);

    // Layer 2: 32 -> 48
    lstm_proj<32, 192, 32><<<2048, 192>>>(h1, Wih2, bih2, bhh2, gx);
    lstm_recur_small<48><<<BB / 2, 192>>>(gx, Whh2, h2);

    // Layer 3: 48 -> 128
    lstm_proj<48, 512, 32><<<2048, 512>>>(h2, Wih3, bih3, bhh3, gx);
    lstm_recur_big<<<BB / 4, 256, SMEM_BIG>>>(gx, Wt3, dec, hn);
}

// round 3
// speedup vs baseline: 2.6404x; 1.0435x over previous
#include <cuda_runtime.h>
#include <math.h>

#define BB 512
#define TT 512

// ---------------- device scratch (allocation-free rule) ----------------
__device__ float g_gx[(size_t)TT * BB * 512];   // gate pre-activations, reused per layer
__device__ float g_h1[(size_t)BB * TT * 32];    // layer1 output
__device__ float g_h2[(size_t)BB * TT * 48];    // layer2 output
__device__ float g_Wt3[128 * 512];              // Whh3 transposed [k][col]

// ---------------- f32x2 helpers ----------------
__device__ __forceinline__ unsigned long long pk2(float a, float b) {
    unsigned long long r;
    asm("mov.b64 %0, {%1,%2};" : "=l"(r) : "f"(a), "f"(b));
    return r;
}
__device__ __forceinline__ void fma2_(unsigned long long& d, unsigned long long a,
                                      unsigned long long b) {
    asm("fma.rn.f32x2 %0, %1, %2, %0;" : "+l"(d) : "l"(a), "l"(b));
}
__device__ __forceinline__ unsigned long long add2_(unsigned long long a,
                                                    unsigned long long b) {
    unsigned long long r;
    asm("add.rn.f32x2 %0, %1, %2;" : "=l"(r) : "l"(a), "l"(b));
    return r;
}
__device__ __forceinline__ float sig_(float x) { return 1.0f / (1.0f + __expf(-x)); }
__device__ __forceinline__ float th_(float x) { return 1.0f - 2.0f / (__expf(2.0f * x) + 1.0f); }

// ---------------------------------------------------------------------------
// Input projection, 1 col/thread (layers 1-2).
// ---------------------------------------------------------------------------
template <int D, int N, int MT>
__global__ void __launch_bounds__(N)
lstm_proj(const float* __restrict__ x, const float* __restrict__ Wih,
          const float* __restrict__ bih, const float* __restrict__ bhh,
          float* __restrict__ gx)
{
    const int col = threadIdx.x;
    float w[D];
#pragma unroll
    for (int k = 0; k < D; k++) w[k] = __ldg(&Wih[col * D + k]);
    const float bsum = __ldg(&bih[col]) + __ldg(&bhh[col]);

    __shared__ float4 xs[MT][D / 4];
    const int ntiles = (BB * TT) / MT;

    for (int tile = blockIdx.x; tile < ntiles; tile += gridDim.x) {
        __syncthreads();
        for (int i = col; i < MT * D / 4; i += N)
            ((float4*)xs)[i] = ((const float4*)x)[(size_t)tile * (MT * D / 4) + i];
        __syncthreads();

#pragma unroll 2
        for (int r = 0; r < MT; r++) {
            float a0 = bsum, a1 = 0.f, a2 = 0.f, a3 = 0.f;
#pragma unroll
            for (int k4 = 0; k4 < D / 4; k4++) {
                float4 v = xs[r][k4];
                a0 = fmaf(w[4 * k4 + 0], v.x, a0);
                a1 = fmaf(w[4 * k4 + 1], v.y, a1);
                a2 = fmaf(w[4 * k4 + 2], v.z, a2);
                a3 = fmaf(w[4 * k4 + 3], v.w, a3);
            }
            int m = tile * MT + r;
            int b = m >> 9, t = m & 511;
            gx[((size_t)t * BB + b) * N + col] = (a0 + a1) + (a2 + a3);
        }
    }
}

// ---------------------------------------------------------------------------
// Input projection for layer 3: N=512 output cols, 256 threads x 2 cols each
// (cols tid and tid+256). Per k4: 1 broadcast LDS.128 feeds 8 FFMA -> FMA-bound.
// ---------------------------------------------------------------------------
template <int D, int MT>
__global__ void __launch_bounds__(256)
lstm_proj3(const float* __restrict__ x, const float* __restrict__ Wih,
           const float* __restrict__ bih, const float* __restrict__ bhh,
           float* __restrict__ gx)
{
    const int tid = threadIdx.x;
    const int cA = tid, cB = tid + 256;

    float wa[D], wb[D];
#pragma unroll
    for (int k = 0; k < D; k++) wa[k] = __ldg(&Wih[cA * D + k]);
#pragma unroll
    for (int k = 0; k < D; k++) wb[k] = __ldg(&Wih[cB * D + k]);
    const float bsA = __ldg(&bih[cA]) + __ldg(&bhh[cA]);
    const float bsB = __ldg(&bih[cB]) + __ldg(&bhh[cB]);

    __shared__ float4 xs[MT][D / 4];
    const int ntiles = (BB * TT) / MT;

    for (int tile = blockIdx.x; tile < ntiles; tile += gridDim.x) {
        __syncthreads();
        for (int i = tid; i < MT * D / 4; i += 256)
            ((float4*)xs)[i] = ((const float4*)x)[(size_t)tile * (MT * D / 4) + i];
        __syncthreads();

#pragma unroll 2
        for (int r = 0; r < MT; r++) {
            float a0 = bsA, a1 = 0.f, a2 = 0.f, a3 = 0.f;
            float b0 = bsB, b1 = 0.f, b2 = 0.f, b3 = 0.f;
#pragma unroll
            for (int k4 = 0; k4 < D / 4; k4++) {
                float4 v = xs[r][k4];
                a0 = fmaf(wa[4 * k4 + 0], v.x, a0);
                a1 = fmaf(wa[4 * k4 + 1], v.y, a1);
                a2 = fmaf(wa[4 * k4 + 2], v.z, a2);
                a3 = fmaf(wa[4 * k4 + 3], v.w, a3);
                b0 = fmaf(wb[4 * k4 + 0], v.x, b0);
                b1 = fmaf(wb[4 * k4 + 1], v.y, b1);
                b2 = fmaf(wb[4 * k4 + 2], v.z, b2);
                b3 = fmaf(wb[4 * k4 + 3], v.w, b3);
            }
            int m = tile * MT + r;
            int b = m >> 9, t = m & 511;
            float* g = gx + ((size_t)t * BB + b) * 512;
            g[cA] = (a0 + a1) + (a2 + a3);
            g[cB] = (b0 + b1) + (b2 + b3);
        }
    }
}

// ---------------------------------------------------------------------------
// Small-layer recurrence (unchanged from passing version).
// ---------------------------------------------------------------------------
template <int H>
__global__ void __launch_bounds__(4 * H)
lstm_recur_small(const float* __restrict__ gx,   // [T][B][4H]
                 const float* __restrict__ Whh,  // [4H][H]
                 float* __restrict__ out)        // [B][T][H]
{
    constexpr int G = 4 * H;
    const int col = threadIdx.x;
    const int b0 = blockIdx.x * 2;

    unsigned long long wh2[H];
#pragma unroll
    for (int k = 0; k < H; k++) {
        float w = __ldg(&Whh[col * H + k]);
        wh2[k] = pk2(w, w);
    }

    __shared__ unsigned long long h2[H];
    __shared__ unsigned long long g2[G];
    if (col < H) h2[col] = 0ull;

    const int erow = col & 1, ecol = col >> 1;
    float c = 0.f;
    __syncthreads();

    for (int t = 0; t < TT; t++) {
        const float* gp = gx + ((size_t)t * BB + b0) * G + col;
        float gx0 = gp[0], gx1 = gp[G];
        unsigned long long a0 = 0ull, a1 = 0ull, a2 = 0ull, a3 = 0ull;
#pragma unroll
        for (int k = 0; k < H; k += 4) {
            fma2_(a0, wh2[k + 0], h2[k + 0]);
            fma2_(a1, wh2[k + 1], h2[k + 1]);
            fma2_(a2, wh2[k + 2], h2[k + 2]);
            fma2_(a3, wh2[k + 3], h2[k + 3]);
        }
        g2[col] = add2_(add2_(add2_(a0, a1), add2_(a2, a3)), pk2(gx0, gx1));
        __syncthreads();

        if (col < 2 * H) {
            const float* gf = (const float*)g2;
            float gi = gf[2 * ecol + erow];
            float gF = gf[2 * (H + ecol) + erow];
            float gg = gf[2 * (2 * H + ecol) + erow];
            float go = gf[2 * (3 * H + ecol) + erow];
            c = sig_(gF) * c + sig_(gi) * th_(gg);
            float h = sig_(go) * th_(c);
            ((float*)h2)[2 * ecol + erow] = h;
            out[((size_t)(b0 + erow) * TT + t) * H + ecol] = h;
        }
        __syncthreads();
    }
}

// ---------------------------------------------------------------------------
// Layer-3 recurrence v2: k-rows [0,64) in smem, [64,128) in registers.
// Crossbar: W 1024 + h-bcast 1024 = 2048 cyc/step == FMA 2048 -> balanced.
// ---------------------------------------------------------------------------
#define KSM 64
#define KRG (128 - KSM)
#define SMEM_BIG (KSM * 512 * 4 + 128 * 16 + 512 * 16)   // 141,312 B

__global__ void __launch_bounds__(256)
lstm_recur_big(const float* __restrict__ gx,   // [T][B][512]
               const float* __restrict__ Wt,   // [128][512] transposed Whh3
               float* __restrict__ out,        // [B][T][128]
               float* __restrict__ hn)         // [B][128]
{
    extern __shared__ char sraw[];
    float2* Wsm = (float2*)sraw;                                   // [KSM][256] float2
    unsigned long long* hp = (unsigned long long*)(sraw + KSM * 512 * 4);        // [128][2]
    unsigned long long* g4 = (unsigned long long*)(sraw + KSM * 512 * 4 + 2048); // [512][2]

    const int tid = threadIdx.x;
    const int b0 = blockIdx.x * 4;
    const int c0 = tid * 2;

    // smem-resident weights: k rows [0, KSM)
    for (int i = tid; i < KSM * 128; i += 256)
        ((float4*)Wsm)[i] = ((const float4*)Wt)[i];
    // register-resident weights: k rows [KSM, 128)
    float2 wg[KRG];
#pragma unroll
    for (int j = 0; j < KRG; j++)
        wg[j] = *(const float2*)(Wt + (size_t)(KSM + j) * 512 + c0);

    hp[tid] = 0ull;  // 256 entries == 128*2

    const int ecol = tid & 127, erp = tid >> 7;
    float cA = 0.f, cB = 0.f;
    __syncthreads();

    for (int t = 0; t < TT; t++) {
        const float* gb = gx + ((size_t)t * BB + b0) * 512 + c0;
        float2 gr0 = *(const float2*)(gb);
        float2 gr1 = *(const float2*)(gb + 512);
        float2 gr2 = *(const float2*)(gb + 1024);
        float2 gr3 = *(const float2*)(gb + 1536);

        unsigned long long A00 = 0, A01 = 0, A10 = 0, A11 = 0;
        unsigned long long B00 = 0, B01 = 0, B10 = 0, B11 = 0;

#pragma unroll 8
        for (int k = 0; k < KSM; k += 2) {
            {
                float2 w = Wsm[k * 256 + tid];
                ulonglong2 h = ((const ulonglong2*)hp)[k];
                unsigned long long w0 = pk2(w.x, w.x), w1 = pk2(w.y, w.y);
                fma2_(A00, w0, h.x); fma2_(A01, w0, h.y);
                fma2_(A10, w1, h.x); fma2_(A11, w1, h.y);
            }
            {
                float2 w = Wsm[(k + 1) * 256 + tid];
                ulonglong2 h = ((const ulonglong2*)hp)[k + 1];
                unsigned long long w0 = pk2(w.x, w.x), w1 = pk2(w.y, w.y);
                fma2_(B00, w0, h.x); fma2_(B01, w0, h.y);
                fma2_(B10, w1, h.x); fma2_(B11, w1, h.y);
            }
        }
#pragma unroll
        for (int j = 0; j < KRG; j++) {
            float2 w = wg[j];
            ulonglong2 h = ((const ulonglong2*)hp)[KSM + j];
            unsigned long long w0 = pk2(w.x, w.x), w1 = pk2(w.y, w.y);
            if (j & 1) { fma2_(B00, w0, h.x); fma2_(B01, w0, h.y);
                         fma2_(B10, w1, h.x); fma2_(B11, w1, h.y); }
            else       { fma2_(A00, w0, h.x); fma2_(A01, w0, h.y);
                         fma2_(A10, w1, h.x); fma2_(A11, w1, h.y); }
        }

        ulonglong2 r0, r1;
        r0.x = add2_(add2_(A00, B00), pk2(gr0.x, gr1.x));
        r0.y = add2_(add2_(A01, B01), pk2(gr2.x, gr3.x));
        r1.x = add2_(add2_(A10, B10), pk2(gr0.y, gr1.y));
        r1.y = add2_(add2_(A11, B11), pk2(gr2.y, gr3.y));
        ((ulonglong2*)g4)[c0]     = r0;
        ((ulonglong2*)g4)[c0 + 1] = r1;
        __syncthreads();

        {
            const float2* gf2 = (const float2*)g4;
            float2 gi = gf2[(ecol      ) * 2 + erp];
            float2 gF = gf2[(ecol + 128) * 2 + erp];
            float2 gg = gf2[(ecol + 256) * 2 + erp];
            float2 go = gf2[(ecol + 384) * 2 + erp];
            cA = sig_(gF.x) * cA + sig_(gi.x) * th_(gg.x);
            cB = sig_(gF.y) * cB + sig_(gi.y) * th_(gg.y);
            float h0 = sig_(go.x) * th_(cA);
            float h1 = sig_(go.y) * th_(cB);
            hp[ecol * 2 + erp] = pk2(h0, h1);
            out[((size_t)(b0 + 2 * erp) * TT + t) * 128 + ecol] = h0;
            out[((size_t)(b0 + 2 * erp + 1) * TT + t) * 128 + ecol] = h1;
            if (t == TT - 1) {
                hn[(size_t)(b0 + 2 * erp) * 128 + ecol] = h0;
                hn[(size_t)(b0 + 2 * erp + 1) * 128 + ecol] = h1;
            }
        }
        __syncthreads();
    }
}

// ---------------------------------------------------------------------------
__global__ void transposeW3(const float* __restrict__ Whh, float* __restrict__ Wt)
{
    int i = blockIdx.x * 256 + threadIdx.x;
    if (i < 128 * 512) {
        int k = i >> 9, col = i & 511;
        Wt[i] = Whh[col * 128 + k];
    }
}

// ---------------------------------------------------------------------------
extern "C" void kernel_launch(void* const* d_in, const int* in_sizes, int n_in,
                              void* d_out, int out_size)
{
    const float* z    = (const float*)d_in[0];
    const float* Wih1 = (const float*)d_in[1];
    const float* Whh1 = (const float*)d_in[2];
    const float* bih1 = (const float*)d_in[3];
    const float* bhh1 = (const float*)d_in[4];
    const float* Wih2 = (const float*)d_in[5];
    const float* Whh2 = (const float*)d_in[6];
    const float* bih2 = (const float*)d_in[7];
    const float* bhh2 = (const float*)d_in[8];
    const float* Wih3 = (const float*)d_in[9];
    const float* Whh3 = (const float*)d_in[10];
    const float* bih3 = (const float*)d_in[11];
    const float* bhh3 = (const float*)d_in[12];

    float* dec = (float*)d_out;                        // [B,T,128]
    float* hn  = dec + (size_t)BB * TT * 128;          // [1,B,128]

    float *gx, *h1, *h2, *Wt3;
    cudaGetSymbolAddress((void**)&gx, g_gx);
    cudaGetSymbolAddress((void**)&h1, g_h1);
    cudaGetSymbolAddress((void**)&h2, g_h2);
    cudaGetSymbolAddress((void**)&Wt3, g_Wt3);

    cudaFuncSetAttribute(lstm_recur_big,
                         cudaFuncAttributeMaxDynamicSharedMemorySize, SMEM_BIG);

    transposeW3<<<256, 256>>>(Whh3, Wt3);

    // Layer 1: 64 -> 32
    lstm_proj<64, 128, 64><<<2048, 128>>>(z, Wih1, bih1, bhh1, gx);
    lstm_recur_small<32><<<BB / 2, 128>>>(gx, Whh1, h1);

    // Layer 2: 32 -> 48
    lstm_proj<32, 192, 64><<<2048, 192>>>(h1, Wih2, bih2, bhh2, gx);
    lstm_recur_small<48><<<BB / 2, 192>>>(gx, Whh2, h2);

    // Layer 3: 48 -> 128
    lstm_proj3<48, 64><<<2048, 256>>>(h2, Wih3, bih3, bhh3, gx);
    lstm_recur_big<<<BB / 4, 256, SMEM_BIG>>>(gx, Wt3, dec, hn);
}

// round 4
// speedup vs baseline: 3.0800x; 1.1665x over previous
#include <cuda_runtime.h>
#include <cuda_fp16.h>
#include <math.h>

#define BB 512
#define TT 512

// ---------------- device scratch (allocation-free rule) ----------------
__device__ __half g_gxh[(size_t)TT * BB * 512];   // gate pre-activations (fp16), reused per layer
__device__ float  g_h1[(size_t)BB * TT * 32];     // layer1 output
__device__ float  g_h2[(size_t)BB * TT * 48];     // layer2 output
__device__ float  g_Wt3[128 * 512];               // Whh3 transposed [k][col]

// ---------------- f32x2 helpers ----------------
__device__ __forceinline__ unsigned long long pk2(float a, float b) {
    unsigned long long r;
    asm("mov.b64 %0, {%1,%2};" : "=l"(r) : "f"(a), "f"(b));
    return r;
}
__device__ __forceinline__ void upk2(unsigned long long v, float& a, float& b) {
    asm("mov.b64 {%0,%1}, %2;" : "=f"(a), "=f"(b) : "l"(v));
}
__device__ __forceinline__ void fma2_(unsigned long long& d, unsigned long long a,
                                      unsigned long long b) {
    asm("fma.rn.f32x2 %0, %1, %2, %0;" : "+l"(d) : "l"(a), "l"(b));
}
__device__ __forceinline__ unsigned long long add2_(unsigned long long a,
                                                    unsigned long long b) {
    unsigned long long r;
    asm("add.rn.f32x2 %0, %1, %2;" : "=l"(r) : "l"(a), "l"(b));
    return r;
}
__device__ __forceinline__ float sig_(float x) { return 1.0f / (1.0f + __expf(-x)); }
__device__ __forceinline__ float th_(float x) { return 1.0f - 2.0f / (__expf(2.0f * x) + 1.0f); }

// ---------------------------------------------------------------------------
// Input projection (all layers): 1 col/thread, f32x2 row-pair accumulation.
// gx written fp16. Col space split across blockIdx.y (for N=512).
//   NT = threads (cols per block), NTOT = total cols (gx stride).
// ---------------------------------------------------------------------------
template <int D, int NT, int NTOT, int MT>
__global__ void __launch_bounds__(NT)
lstm_projH(const float* __restrict__ x, const float* __restrict__ Wih,
           const float* __restrict__ bih, const float* __restrict__ bhh,
           __half* __restrict__ gx)
{
    const int tid = threadIdx.x;
    const int col = blockIdx.y * NT + tid;

    // packed weights: w2[k] = (w[k], w[k])
    unsigned long long w2[D];
#pragma unroll
    for (int k = 0; k < D; k++) {
        float w = __ldg(&Wih[col * D + k]);
        w2[k] = pk2(w, w);
    }
    const float bsum = __ldg(&bih[col]) + __ldg(&bhh[col]);
    const unsigned long long b2 = pk2(bsum, bsum);

    __shared__ float4 xs[MT][D / 4];
    const int ntiles = (BB * TT) / MT;

    for (int tile = blockIdx.x; tile < ntiles; tile += gridDim.x) {
        __syncthreads();
        for (int i = tid; i < MT * D / 4; i += NT)
            ((float4*)xs)[i] = ((const float4*)x)[(size_t)tile * (MT * D / 4) + i];
        __syncthreads();

#pragma unroll 2
        for (int r = 0; r < MT; r += 2) {
            unsigned long long a0 = b2, a1 = 0ull, a2 = 0ull, a3 = 0ull;
#pragma unroll
            for (int k4 = 0; k4 < D / 4; k4++) {
                float4 v0 = xs[r][k4];
                float4 v1 = xs[r + 1][k4];
                fma2_(a0, w2[4 * k4 + 0], pk2(v0.x, v1.x));
                fma2_(a1, w2[4 * k4 + 1], pk2(v0.y, v1.y));
                fma2_(a2, w2[4 * k4 + 2], pk2(v0.z, v1.z));
                fma2_(a3, w2[4 * k4 + 3], pk2(v0.w, v1.w));
            }
            unsigned long long s = add2_(add2_(a0, a1), add2_(a2, a3));
            float g0, g1;
            upk2(s, g0, g1);
            int m = tile * MT + r;
            int b = m >> 9, t = m & 511;           // rows r, r+1 -> t, t+1 (same b)
            gx[((size_t)t * BB + b) * NTOT + col]       = __float2half(g0);
            gx[((size_t)(t + 1) * BB + b) * NTOT + col] = __float2half(g1);
        }
    }
}

// ---------------------------------------------------------------------------
// Small-layer recurrence (L1: H=32, L2: H=48), fp16 gx, depth-2 prefetch.
// ---------------------------------------------------------------------------
template <int H>
__global__ void __launch_bounds__(4 * H)
lstm_recur_small(const __half* __restrict__ gx,  // [T][B][4H] fp16
                 const float* __restrict__ Whh,  // [4H][H]
                 float* __restrict__ out)        // [B][T][H]
{
    constexpr int G = 4 * H;
    const int col = threadIdx.x;
    const int b0 = blockIdx.x * 2;

    unsigned long long wh2[H];
#pragma unroll
    for (int k = 0; k < H; k++) {
        float w = __ldg(&Whh[col * H + k]);
        wh2[k] = pk2(w, w);
    }

    __shared__ unsigned long long h2[H];
    __shared__ unsigned long long g2[G];
    if (col < H) h2[col] = 0ull;

    const int erow = col & 1, ecol = col >> 1;
    float c = 0.f;

    const __half* gbase = gx + (size_t)b0 * G + col;
    const size_t tstride = (size_t)BB * G;

    // depth-2 prefetch
    __half A0 = gbase[0], A1 = gbase[G];
    __half B0 = gbase[tstride], B1 = gbase[tstride + G];
    __syncthreads();

    for (int t = 0; t < TT; t++) {
        __half C0 = __float2half(0.f), C1 = C0;
        if (t + 2 < TT) {
            const __half* gp = gbase + (size_t)(t + 2) * tstride;
            C0 = gp[0]; C1 = gp[G];
        }
        unsigned long long a0 = 0ull, a1 = 0ull, a2 = 0ull, a3 = 0ull;
#pragma unroll
        for (int k = 0; k < H; k += 4) {
            fma2_(a0, wh2[k + 0], h2[k + 0]);
            fma2_(a1, wh2[k + 1], h2[k + 1]);
            fma2_(a2, wh2[k + 2], h2[k + 2]);
            fma2_(a3, wh2[k + 3], h2[k + 3]);
        }
        g2[col] = add2_(add2_(add2_(a0, a1), add2_(a2, a3)),
                        pk2(__half2float(A0), __half2float(A1)));
        A0 = B0; A1 = B1; B0 = C0; B1 = C1;
        __syncthreads();

        if (col < 2 * H) {
            const float* gf = (const float*)g2;
            float gi = gf[2 * ecol + erow];
            float gF = gf[2 * (H + ecol) + erow];
            float gg = gf[2 * (2 * H + ecol) + erow];
            float go = gf[2 * (3 * H + ecol) + erow];
            c = sig_(gF) * c + sig_(gi) * th_(gg);
            float h = sig_(go) * th_(c);
            ((float*)h2)[2 * ecol + erow] = h;
            out[((size_t)(b0 + erow) * TT + t) * H + ecol] = h;
        }
        __syncthreads();
    }
}

// ---------------------------------------------------------------------------
// Layer-3 recurrence: KSM=96 k-rows in smem, KRG=32 in registers (no spill).
// fp16 gx with depth-2 prefetch.
// ---------------------------------------------------------------------------
#define KSM 96
#define KRG (128 - KSM)
#define SMEM_BIG (KSM * 512 * 4 + 128 * 16 + 512 * 16)   // 206,848 B

__global__ void __launch_bounds__(256)
lstm_recur_big(const __half* __restrict__ gx,  // [T][B][512] fp16
               const float* __restrict__ Wt,   // [128][512] transposed Whh3
               float* __restrict__ out,        // [B][T][128]
               float* __restrict__ hn)         // [B][128]
{
    extern __shared__ char sraw[];
    float2* Wsm = (float2*)sraw;                                         // [KSM][256]
    unsigned long long* hp = (unsigned long long*)(sraw + KSM * 512 * 4);        // [128][2]
    unsigned long long* g4 = (unsigned long long*)(sraw + KSM * 512 * 4 + 2048); // [512][2]

    const int tid = threadIdx.x;
    const int b0 = blockIdx.x * 4;
    const int c0 = tid * 2;

    for (int i = tid; i < KSM * 128; i += 256)
        ((float4*)Wsm)[i] = ((const float4*)Wt)[i];
    float2 wg[KRG];
#pragma unroll
    for (int j = 0; j < KRG; j++)
        wg[j] = *(const float2*)(Wt + (size_t)(KSM + j) * 512 + c0);

    hp[tid] = 0ull;

    const int ecol = tid & 127, erp = tid >> 7;
    float cA = 0.f, cB = 0.f;

    const __half2* gb = (const __half2*)(gx + (size_t)b0 * 512 + c0);
    const size_t tstride = (size_t)BB * 256;   // in half2 units

    __half2 pA0 = gb[0], pA1 = gb[256], pA2 = gb[512], pA3 = gb[768];
    __half2 pB0 = gb[tstride + 0], pB1 = gb[tstride + 256],
            pB2 = gb[tstride + 512], pB3 = gb[tstride + 768];
    __syncthreads();

    for (int t = 0; t < TT; t++) {
        __half2 pC0, pC1, pC2, pC3;
        pC0 = pC1 = pC2 = pC3 = __float2half2_rn(0.f);
        if (t + 2 < TT) {
            const __half2* gp = gb + (size_t)(t + 2) * tstride;
            pC0 = gp[0]; pC1 = gp[256]; pC2 = gp[512]; pC3 = gp[768];
        }

        unsigned long long A00 = 0, A01 = 0, A10 = 0, A11 = 0;
        unsigned long long B00 = 0, B01 = 0, B10 = 0, B11 = 0;

#pragma unroll 8
        for (int k = 0; k < KSM; k += 2) {
            {
                float2 w = Wsm[k * 256 + tid];
                ulonglong2 h = ((const ulonglong2*)hp)[k];
                unsigned long long w0 = pk2(w.x, w.x), w1 = pk2(w.y, w.y);
                fma2_(A00, w0, h.x); fma2_(A01, w0, h.y);
                fma2_(A10, w1, h.x); fma2_(A11, w1, h.y);
            }
            {
                float2 w = Wsm[(k + 1) * 256 + tid];
                ulonglong2 h = ((const ulonglong2*)hp)[k + 1];
                unsigned long long w0 = pk2(w.x, w.x), w1 = pk2(w.y, w.y);
                fma2_(B00, w0, h.x); fma2_(B01, w0, h.y);
                fma2_(B10, w1, h.x); fma2_(B11, w1, h.y);
            }
        }
#pragma unroll
        for (int j = 0; j < KRG; j++) {
            float2 w = wg[j];
            ulonglong2 h = ((const ulonglong2*)hp)[KSM + j];
            unsigned long long w0 = pk2(w.x, w.x), w1 = pk2(w.y, w.y);
            if (j & 1) { fma2_(B00, w0, h.x); fma2_(B01, w0, h.y);
                         fma2_(B10, w1, h.x); fma2_(B11, w1, h.y); }
            else       { fma2_(A00, w0, h.x); fma2_(A01, w0, h.y);
                         fma2_(A10, w1, h.x); fma2_(A11, w1, h.y); }
        }

        float2 f0 = __half22float2(pA0), f1 = __half22float2(pA1);
        float2 f2 = __half22float2(pA2), f3 = __half22float2(pA3);
        pA0 = pB0; pA1 = pB1; pA2 = pB2; pA3 = pB3;
        pB0 = pC0; pB1 = pC1; pB2 = pC2; pB3 = pC3;

        ulonglong2 r0, r1;
        r0.x = add2_(add2_(A00, B00), pk2(f0.x, f1.x));
        r0.y = add2_(add2_(A01, B01), pk2(f2.x, f3.x));
        r1.x = add2_(add2_(A10, B10), pk2(f0.y, f1.y));
        r1.y = add2_(add2_(A11, B11), pk2(f2.y, f3.y));
        ((ulonglong2*)g4)[c0]     = r0;
        ((ulonglong2*)g4)[c0 + 1] = r1;
        __syncthreads();

        {
            const float2* gf2 = (const float2*)g4;
            float2 gi = gf2[(ecol      ) * 2 + erp];
            float2 gF = gf2[(ecol + 128) * 2 + erp];
            float2 gg = gf2[(ecol + 256) * 2 + erp];
            float2 go = gf2[(ecol + 384) * 2 + erp];
            cA = sig_(gF.x) * cA + sig_(gi.x) * th_(gg.x);
            cB = sig_(gF.y) * cB + sig_(gi.y) * th_(gg.y);
            float h0 = sig_(go.x) * th_(cA);
            float h1 = sig_(go.y) * th_(cB);
            hp[ecol * 2 + erp] = pk2(h0, h1);
            out[((size_t)(b0 + 2 * erp) * TT + t) * 128 + ecol] = h0;
            out[((size_t)(b0 + 2 * erp + 1) * TT + t) * 128 + ecol] = h1;
            if (t == TT - 1) {
                hn[(size_t)(b0 + 2 * erp) * 128 + ecol] = h0;
                hn[(size_t)(b0 + 2 * erp + 1) * 128 + ecol] = h1;
            }
        }
        __syncthreads();
    }
}

// ---------------------------------------------------------------------------
__global__ void transposeW3(const float* __restrict__ Whh, float* __restrict__ Wt)
{
    int i = blockIdx.x * 256 + threadIdx.x;
    if (i < 128 * 512) {
        int k = i >> 9, col = i & 511;
        Wt[i] = Whh[col * 128 + k];
    }
}

// ---------------------------------------------------------------------------
extern "C" void kernel_launch(void* const* d_in, const int* in_sizes, int n_in,
                              void* d_out, int out_size)
{
    const float* z    = (const float*)d_in[0];
    const float* Wih1 = (const float*)d_in[1];
    const float* Whh1 = (const float*)d_in[2];
    const float* bih1 = (const float*)d_in[3];
    const float* bhh1 = (const float*)d_in[4];
    const float* Wih2 = (const float*)d_in[5];
    const float* Whh2 = (const float*)d_in[6];
    const float* bih2 = (const float*)d_in[7];
    const float* bhh2 = (const float*)d_in[8];
    const float* Wih3 = (const float*)d_in[9];
    const float* Whh3 = (const float*)d_in[10];
    const float* bih3 = (const float*)d_in[11];
    const float* bhh3 = (const float*)d_in[12];

    float* dec = (float*)d_out;                        // [B,T,128]
    float* hn  = dec + (size_t)BB * TT * 128;          // [1,B,128]

    __half* gx;
    float *h1, *h2, *Wt3;
    cudaGetSymbolAddress((void**)&gx, g_gxh);
    cudaGetSymbolAddress((void**)&h1, g_h1);
    cudaGetSymbolAddress((void**)&h2, g_h2);
    cudaGetSymbolAddress((void**)&Wt3, g_Wt3);

    cudaFuncSetAttribute(lstm_recur_big,
                         cudaFuncAttributeMaxDynamicSharedMemorySize, SMEM_BIG);

    transposeW3<<<256, 256>>>(Whh3, Wt3);

    // Layer 1: 64 -> 32
    lstm_projH<64, 128, 128, 64><<<dim3(2048, 1), 128>>>(z, Wih1, bih1, bhh1, gx);
    lstm_recur_small<32><<<BB / 2, 128>>>(gx, Whh1, h1);

    // Layer 2: 32 -> 48
    lstm_projH<32, 192, 192, 64><<<dim3(2048, 1), 192>>>(h1, Wih2, bih2, bhh2, gx);
    lstm_recur_small<48><<<BB / 2, 192>>>(gx, Whh2, h2);

    // Layer 3: 48 -> 128
    lstm_projH<48, 256, 512, 64><<<dim3(2048, 2), 256>>>(h2, Wih3, bih3, bhh3, gx);
    lstm_recur_big<<<BB / 4, 256, SMEM_BIG>>>(gx, Wt3, dec, hn);
}